// round 16
// baseline (speedup 1.0000x reference)
#include <cuda_runtime.h>
#include <cuda_bf16.h>
#include <cstdint>
#include <math.h>

// Problem constants
constexpr int B_  = 2;
constexpr int S_  = 2048;
constexpr int D_  = 2048;
constexpr int H_  = 16;
constexpr int HD_ = 128;

// ---- pre-split bf16 scratch (device globals; no allocation allowed) ----
__device__ __nv_bfloat16 g_xh [(size_t)B_ * S_ * D_], g_xl [(size_t)B_ * S_ * D_];
__device__ __nv_bfloat16 g_wqh[(size_t)D_ * D_],      g_wql[(size_t)D_ * D_];
__device__ __nv_bfloat16 g_wkh[(size_t)D_ * HD_],     g_wkl[(size_t)D_ * HD_];
__device__ __nv_bfloat16 g_wvh[(size_t)D_ * HD_],     g_wvl[(size_t)D_ * HD_];
__device__ __nv_bfloat16 g_woh[(size_t)D_ * D_],      g_wol[(size_t)D_ * D_];
__device__ __nv_bfloat16 g_qh [(size_t)B_ * S_ * D_], g_ql [(size_t)B_ * S_ * D_];
__device__ __nv_bfloat16 g_kh [(size_t)B_ * S_ * HD_], g_kl [(size_t)B_ * S_ * HD_];
__device__ __nv_bfloat16 g_vh [(size_t)B_ * S_ * HD_], g_vl [(size_t)B_ * S_ * HD_];
__device__ __nv_bfloat16 g_ath[(size_t)B_ * S_ * D_], g_atl[(size_t)B_ * S_ * D_];

// ===========================================================================
// PTX helpers — baseline ISA only (mma.sync sm_80+, ldmatrix, cp.async).
// ===========================================================================
__device__ __forceinline__ uint32_t smem_u32(const void* p) {
    uint32_t a;
    asm("{ .reg .u64 t; cvta.to.shared.u64 t, %1; cvt.u32.u64 %0, t; }"
        : "=r"(a) : "l"(p));
    return a;
}
__device__ __forceinline__ void ldsm_x4(uint32_t* r, uint32_t addr) {
    asm volatile("ldmatrix.sync.aligned.m8n8.x4.shared.b16 {%0,%1,%2,%3}, [%4];"
                 : "=r"(r[0]), "=r"(r[1]), "=r"(r[2]), "=r"(r[3]) : "r"(addr));
}
__device__ __forceinline__ void ldsm_x4_t(uint32_t* r, uint32_t addr) {
    asm volatile("ldmatrix.sync.aligned.m8n8.x4.trans.shared.b16 {%0,%1,%2,%3}, [%4];"
                 : "=r"(r[0]), "=r"(r[1]), "=r"(r[2]), "=r"(r[3]) : "r"(addr));
}
__device__ __forceinline__ void mma16816(float* c, const uint32_t* a, const uint32_t* b) {
    asm volatile(
        "mma.sync.aligned.m16n8k16.row.col.f32.bf16.bf16.f32 "
        "{%0,%1,%2,%3}, {%4,%5,%6,%7}, {%8,%9}, {%0,%1,%2,%3};"
        : "+f"(c[0]), "+f"(c[1]), "+f"(c[2]), "+f"(c[3])
        : "r"(a[0]), "r"(a[1]), "r"(a[2]), "r"(a[3]), "r"(b[0]), "r"(b[1]));
}
__device__ __forceinline__ void cp16(uint32_t dst, const void* src) {
    asm volatile("cp.async.cg.shared.global [%0], [%1], 16;" :: "r"(dst), "l"(src));
}
#define CP_COMMIT() asm volatile("cp.async.commit_group;" ::: "memory")
template<int N> __device__ __forceinline__ void cp_wait() {
    asm volatile("cp.async.wait_group %0;" :: "n"(N) : "memory");
}
__device__ __forceinline__ void l2_prefetch(const void* p) {
    asm volatile("prefetch.global.L2 [%0];" :: "l"(p));
}

__device__ __forceinline__ void split4(float4 v, uint2& hp, uint2& lp) {
    __nv_bfloat16 hx = __float2bfloat16(v.x), hy = __float2bfloat16(v.y);
    __nv_bfloat16 hz = __float2bfloat16(v.z), hw = __float2bfloat16(v.w);
    __nv_bfloat16 lx = __float2bfloat16(v.x - __bfloat162float(hx));
    __nv_bfloat16 ly = __float2bfloat16(v.y - __bfloat162float(hy));
    __nv_bfloat16 lz = __float2bfloat16(v.z - __bfloat162float(hz));
    __nv_bfloat16 lw = __float2bfloat16(v.w - __bfloat162float(hw));
    hp.x = (uint32_t)__bfloat16_as_ushort(hx) | ((uint32_t)__bfloat16_as_ushort(hy) << 16);
    hp.y = (uint32_t)__bfloat16_as_ushort(hz) | ((uint32_t)__bfloat16_as_ushort(hw) << 16);
    lp.x = (uint32_t)__bfloat16_as_ushort(lx) | ((uint32_t)__bfloat16_as_ushort(ly) << 16);
    lp.y = (uint32_t)__bfloat16_as_ushort(lz) | ((uint32_t)__bfloat16_as_ushort(lw) << 16);
}
__device__ __forceinline__ void split2(float x, float y, uint32_t& hi, uint32_t& lo) {
    __nv_bfloat16 hx = __float2bfloat16(x), hy = __float2bfloat16(y);
    __nv_bfloat16 lx = __float2bfloat16(x - __bfloat162float(hx));
    __nv_bfloat16 ly = __float2bfloat16(y - __bfloat162float(hy));
    hi = (uint32_t)__bfloat16_as_ushort(hx) | ((uint32_t)__bfloat16_as_ushort(hy) << 16);
    lo = (uint32_t)__bfloat16_as_ushort(lx) | ((uint32_t)__bfloat16_as_ushort(ly) << 16);
}

// exp2 on the FMA pipe: deg-5 poly, rel err ~2e-6.
__device__ __forceinline__ float exp2p(float y) {
    y = fmaxf(y, -126.0f);
    float k = rintf(y);
    float f = y - k;
    float p = 1.3333558146e-3f;
    p = fmaf(p, f, 9.6181291058e-3f);
    p = fmaf(p, f, 5.5504108664e-2f);
    p = fmaf(p, f, 2.4022650696e-1f);
    p = fmaf(p, f, 6.9314718056e-1f);
    p = fmaf(p, f, 1.0f);
    return p * __int_as_float(((int)k + 127) << 23);
}
// exp2 on the MUFU pipe (pipe-balance with exp2p). Proven accuracy-safe.
__device__ __forceinline__ float ex2m(float y) {
    float r;
    asm("ex2.approx.ftz.f32 %0, %1;" : "=f"(r) : "f"(y));
    return r;
}

// ===========================================================================
// Prepass (single launch): fp32 -> (hi, lo) bf16, all 5 arrays.
// ===========================================================================
__global__ void split_all(const float* __restrict__ x,  const float* __restrict__ wq,
                          const float* __restrict__ wk, const float* __restrict__ wv,
                          const float* __restrict__ wo)
{
    int bx = blockIdx.x;
    const float* src; __nv_bfloat16 *h, *l; int off;
    if (bx < 8192)       { src = x;  h = g_xh;  l = g_xl;  off = bx; }
    else if (bx < 12288) { src = wq; h = g_wqh; l = g_wql; off = bx - 8192; }
    else if (bx < 12544) { src = wk; h = g_wkh; l = g_wkl; off = bx - 12288; }
    else if (bx < 12800) { src = wv; h = g_wvh; l = g_wvl; off = bx - 12544; }
    else                 { src = wo; h = g_woh; l = g_wol; off = bx - 12800; }
    size_t i = ((size_t)off * 256 + threadIdx.x) * 4;
    float4 v = *(const float4*)(src + i);
    uint2 hp, lp;
    split4(v, hp, lp);
    *(uint2*)(h + i) = hp;
    *(uint2*)(l + i) = lp;
}

// ===========================================================================
// tc_gemm3: bf16-split HMMA GEMM, cp.async 3-stage pipe, region-decoded.
// (unchanged — tensor 57%)
// ===========================================================================
constexpr int KC2  = 32;
constexpr int SAe  = 40;
constexpr int SBe  = 136;
constexpr int AL_E = 128 * SAe;
constexpr int BH_E = 2 * 128 * SAe;
constexpr int BL_E = BH_E + KC2 * SBe;
constexpr int STG_E = BL_E + KC2 * SBe;
constexpr int SMEM_G2 = 3 * STG_E * 2;

__global__ __launch_bounds__(256)
void tc_gemm3(int mode, const float* __restrict__ biasQ, const float* __restrict__ biasK,
              const float* __restrict__ biasV, float* __restrict__ CfOut)
{
    const int bx = blockIdx.x;
    const __nv_bfloat16 *Agh, *Agl, *Bgh, *Bgl;
    const float* bia;
    __nv_bfloat16 *Ch = nullptr, *Cl = nullptr;
    float* Cf = nullptr;
    int NW, colL;
    float osc = 1.0f;
    if (mode == 0) {
        Agh = g_xh; Agl = g_xl;
        if (bx < 16) {
            Bgh = g_wqh; Bgl = g_wql; bia = biasQ; NW = D_;  colL = bx * 128;
            Ch = g_qh; Cl = g_ql; osc = 0.08838834764831845f;
        } else if (bx == 16) {
            Bgh = g_wkh; Bgl = g_wkl; bia = biasK; NW = HD_; colL = 0;
            Ch = g_kh; Cl = g_kl;
        } else {
            Bgh = g_wvh; Bgl = g_wvl; bia = biasV; NW = HD_; colL = 0;
            Ch = g_vh; Cl = g_vl;
        }
    } else {
        Agh = g_ath; Agl = g_atl;
        Bgh = g_woh; Bgl = g_wol; bia = biasQ; NW = D_; colL = bx * 128;
        Cf = CfOut;
    }
    const int K = D_;

    extern __shared__ unsigned short smu[];
    const uint32_t sb = smem_u32(smu);
    const int tid  = threadIdx.x;
    const int wid  = tid >> 5;
    const int lane = tid & 31;
    const int row0 = blockIdx.y * 128;

    const int wm = wid >> 2;
    const int wn = wid & 3;
    const int la = lane & 15;
    const int lb = lane >> 4;

    uint32_t offA[4], offB4[2];
#pragma unroll
    for (int mi = 0; mi < 4; ++mi)
        offA[mi] = (uint32_t)(((wm * 64 + mi * 16 + la) * SAe + lb * 8) * 2);
#pragma unroll
    for (int p = 0; p < 2; ++p)
        offB4[p] = (uint32_t)((la * SBe + wn * 32 + p * 16 + lb * 8) * 2);

    auto issue = [&](int c, int stg) {
        const int kc = c * KC2;
        const uint32_t sbase = sb + (uint32_t)(stg * STG_E) * 2;
#pragma unroll
        for (int u = 0; u < 2; ++u) {
            int ci2 = u * 256 + tid;
            int r = ci2 >> 2, p = ci2 & 3;
            uint32_t doff = (uint32_t)((r * SAe + p * 8) * 2);
            const size_t gsrc = (size_t)(row0 + r) * K + kc + p * 8;
            cp16(sbase + doff, Agh + gsrc);
            cp16(sbase + AL_E * 2 + doff, Agl + gsrc);
        }
#pragma unroll
        for (int u = 0; u < 2; ++u) {
            int ci2 = u * 256 + tid;
            int k = ci2 >> 4, p = ci2 & 15;
            uint32_t doff = (uint32_t)((k * SBe + p * 8) * 2);
            const size_t gsrc = (size_t)(kc + k) * NW + colL + p * 8;
            cp16(sbase + BH_E * 2 + doff, Bgh + gsrc);
            cp16(sbase + BL_E * 2 + doff, Bgl + gsrc);
        }
    };

    float acc[4][4][4];
#pragma unroll
    for (int mi = 0; mi < 4; ++mi)
#pragma unroll
        for (int ni = 0; ni < 4; ++ni)
#pragma unroll
            for (int r = 0; r < 4; ++r) acc[mi][ni][r] = 0.0f;

    issue(0, 0); CP_COMMIT();
    issue(1, 1); CP_COMMIT();

    const int NCH = K / KC2;
    for (int ci = 0; ci < NCH; ++ci) {
        cp_wait<1>();
        __syncthreads();
        if (ci + 2 < NCH) { issue(ci + 2, (ci + 2) % 3); CP_COMMIT(); }

        const uint32_t bAh = sb + (uint32_t)((ci % 3) * STG_E) * 2;
        const uint32_t bAl = bAh + AL_E * 2;
        const uint32_t bBh = sb + (uint32_t)((ci % 3) * STG_E + BH_E) * 2;
        const uint32_t bBl = bBh + (BL_E - BH_E) * 2;

#pragma unroll
        for (int kk = 0; kk < 2; ++kk) {
            const uint32_t dA = (uint32_t)(kk * 16 * 2);
            const uint32_t dB = (uint32_t)(kk * 16 * SBe * 2);
            uint32_t ah[4][4], al[4][4], bh[4][2], bl[4][2], t4[4];
#pragma unroll
            for (int mi = 0; mi < 4; ++mi) {
                ldsm_x4(ah[mi], bAh + offA[mi] + dA);
                ldsm_x4(al[mi], bAl + offA[mi] + dA);
            }
#pragma unroll
            for (int p = 0; p < 2; ++p) {
                ldsm_x4_t(t4, bBh + offB4[p] + dB);
                bh[2 * p][0] = t4[0]; bh[2 * p][1] = t4[1];
                bh[2 * p + 1][0] = t4[2]; bh[2 * p + 1][1] = t4[3];
                ldsm_x4_t(t4, bBl + offB4[p] + dB);
                bl[2 * p][0] = t4[0]; bl[2 * p][1] = t4[1];
                bl[2 * p + 1][0] = t4[2]; bl[2 * p + 1][1] = t4[3];
            }
#pragma unroll
            for (int mi = 0; mi < 4; ++mi)
#pragma unroll
                for (int ni = 0; ni < 4; ++ni)
                    mma16816(acc[mi][ni], ah[mi], bh[ni]);
#pragma unroll
            for (int mi = 0; mi < 4; ++mi)
#pragma unroll
                for (int ni = 0; ni < 4; ++ni)
                    mma16816(acc[mi][ni], ah[mi], bl[ni]);
#pragma unroll
            for (int mi = 0; mi < 4; ++mi)
#pragma unroll
                for (int ni = 0; ni < 4; ++ni)
                    mma16816(acc[mi][ni], al[mi], bh[ni]);
        }
    }

    const int g = lane >> 2, t = lane & 3;
    if (Cf) {
#pragma unroll
        for (int mi = 0; mi < 4; ++mi)
#pragma unroll
            for (int ni = 0; ni < 4; ++ni) {
                int row = row0 + wm * 64 + mi * 16 + g;
                int col = colL + wn * 32 + ni * 8 + 2 * t;
                float b0v = bia[col], b1v = bia[col + 1];
                *(float2*)&Cf[(size_t)row * NW + col] =
                    make_float2(acc[mi][ni][0] + b0v, acc[mi][ni][1] + b1v);
                *(float2*)&Cf[(size_t)(row + 8) * NW + col] =
                    make_float2(acc[mi][ni][2] + b0v, acc[mi][ni][3] + b1v);
            }
    } else {
#pragma unroll
        for (int mi = 0; mi < 4; ++mi)
#pragma unroll
            for (int ni = 0; ni < 4; ++ni) {
                int row = row0 + wm * 64 + mi * 16 + g;
                int col = colL + wn * 32 + ni * 8 + 2 * t;
                float b0v = bia[col], b1v = bia[col + 1];
                uint32_t hi, lo;
                split2((acc[mi][ni][0] + b0v) * osc, (acc[mi][ni][1] + b1v) * osc, hi, lo);
                *(uint32_t*)(Ch + (size_t)row * NW + col) = hi;
                *(uint32_t*)(Cl + (size_t)row * NW + col) = lo;
                split2((acc[mi][ni][2] + b0v) * osc, (acc[mi][ni][3] + b1v) * osc, hi, lo);
                *(uint32_t*)(Ch + (size_t)(row + 8) * NW + col) = hi;
                *(uint32_t*)(Cl + (size_t)(row + 8) * NW + col) = lo;
            }
    }
}

// ===========================================================================
// flash_hmma9: ONE 256-thread CTA = 8 warps/SM WITHOUT a register cap.
// Br=128 (8 warps x 16 q-rows, per-warp work identical to R13), Bc=64.
// smem 104448 B: Q occupies [0, 34816) elems; after Q-frags move to
// registers that region becomes the K double-buffer (two 17408-elem bufs);
// V single-buffered at [34816, 52224). Prologue: Q -> frags -> K0.
// ===========================================================================
constexpr int FSe6  = 136;
constexpr int KB0_E = 0;                   // K buffer 0 (Q-hi region)
constexpr int KB1_E = 17408;               // K buffer 1 (Q-lo region)
constexpr int VH_E6 = 34816;
constexpr int VL_E6 = 43520;
constexpr int HALF_T = 8704;               // one hi (or lo) 64-row tensor: 64*136
constexpr int QLO_E  = 17408;              // Q lo offset (elems)
constexpr int SMEM_FL6 = 52224 * 2;        // 104448 B

__global__ __launch_bounds__(256, 1)
void flash_hmma9(const float* __restrict__ mask)
{
    extern __shared__ unsigned short smu[];
    const uint32_t sb = smem_u32(smu);
    const int tid  = threadIdx.x;
    const int wid  = tid >> 5;
    const int lane = tid & 31;
    const int q0 = blockIdx.x * 128;
    const int h  = blockIdx.y;
    const int b  = blockIdx.z;
    const int qr = wid * 16;
    const int g  = lane >> 2;
    const int t  = lane & 3;
    const int la = lane & 15;
    const int lb = lane >> 4;
    const float L2E = 1.4426950408889634f;

    // 64-row split tensor loader: 1024 16B-chunks over 256 threads (hi+lo)
    auto issueT = [&](const __nv_bfloat16* srcH, const __nv_bfloat16* srcL,
                      uint32_t dstE, int row0g) {
#pragma unroll
        for (int u = 0; u < 4; ++u) {
            int ci2 = u * 256 + tid;
            int r = ci2 >> 4, p = ci2 & 15;
            const size_t gsrc = ((size_t)(b * S_ + row0g + r)) * HD_ + p * 8;
            uint32_t doff = (uint32_t)((r * FSe6 + p * 8) * 2);
            cp16(sb + dstE * 2 + doff, srcH + gsrc);
            cp16(sb + (dstE + HALF_T) * 2 + doff, srcL + gsrc);
        }
    };

    // ---- prologue: Q (128 rows, hi+lo) -> [0, 34816) ----
#pragma unroll
    for (int u = 0; u < 8; ++u) {
        int ci2 = u * 256 + tid;
        int r = ci2 >> 4, p = ci2 & 15;
        const size_t gsrc = ((size_t)(b * S_ + q0 + r)) * D_ + h * HD_ + p * 8;
        uint32_t doff = (uint32_t)((r * FSe6 + p * 8) * 2);
        cp16(sb + doff, g_qh + gsrc);
        cp16(sb + QLO_E * 2 + doff, g_ql + gsrc);
    }
    CP_COMMIT();
    cp_wait<0>();
    __syncthreads();

    // ---- Q A-frags to registers (persist); Q region then becomes K bufs ----
    uint32_t ah[8][4], al[8][4];
#pragma unroll
    for (int ks = 0; ks < 8; ++ks) {
        uint32_t ad = sb + (uint32_t)(((qr + la) * FSe6 + ks * 16 + lb * 8) * 2);
        ldsm_x4(ah[ks], ad);
        ldsm_x4(al[ks], ad + QLO_E * 2);
    }
    __syncthreads();                        // all warps done reading Q region

    issueT(g_kh, g_kl, KB0_E, 0);           // K0 -> buffer 0
    CP_COMMIT();

    float m0 = -1e30f, m1 = -1e30f, l0 = 0.0f, l1 = 0.0f;
    float o[16][4];
#pragma unroll
    for (int nf = 0; nf < 16; ++nf)
#pragma unroll
        for (int r = 0; r < 4; ++r) o[nf][r] = 0.0f;

    constexpr int NT = S_ / 64;
    for (int ci = 0; ci < NT; ++ci) {
        cp_wait<0>();                       // K_ci resident
        __syncthreads();                    // V / K-buf overwrite safety

        const uint32_t kBase = (ci & 1) ? (uint32_t)KB1_E : (uint32_t)KB0_E;

        issueT(g_vh, g_vl, VH_E6, ci * 64); // V_ci (own group)
        CP_COMMIT();
        if (ci + 1 < NT) {
            issueT(g_kh, g_kl, ((ci + 1) & 1) ? KB1_E : KB0_E, (ci + 1) * 64);
            CP_COMMIT();
        }

        const int kv0 = ci * 64;
        const float* mp0 = mask + ((size_t)b * S_ + (q0 + qr + g)) * S_ + kv0 + 2 * t;
        const float* mp1 = mp0 + 8 * (size_t)S_;
        if (ci + 1 < NT) {
            l2_prefetch(mp0 + 64); l2_prefetch(mp0 + 96);
            l2_prefetch(mp1 + 64); l2_prefetch(mp1 + 96);
        }

        // ---- S = Q @ K^T (hh + lh + hl) ----
        float s[8][4];
#pragma unroll
        for (int j = 0; j < 8; ++j)
#pragma unroll
            for (int r = 0; r < 4; ++r) s[j][r] = 0.0f;

#pragma unroll
        for (int ks = 0; ks < 8; ++ks) {
            uint32_t t4[4], khf[8][2];
#pragma unroll
            for (int gg = 0; gg < 4; ++gg) {
                uint32_t ad = sb + (uint32_t)((kBase + (gg * 16 + la) * FSe6 + ks * 16 + lb * 8) * 2);
                ldsm_x4(t4, ad);
                khf[2 * gg][0] = t4[0]; khf[2 * gg][1] = t4[2];
                khf[2 * gg + 1][0] = t4[1]; khf[2 * gg + 1][1] = t4[3];
            }
#pragma unroll
            for (int j = 0; j < 8; ++j) mma16816(s[j], ah[ks], khf[j]);
#pragma unroll
            for (int j = 0; j < 8; ++j) mma16816(s[j], al[ks], khf[j]);
            uint32_t klf[8][2];
#pragma unroll
            for (int gg = 0; gg < 4; ++gg) {
                uint32_t ad = sb + (uint32_t)((kBase + HALF_T + (gg * 16 + la) * FSe6 + ks * 16 + lb * 8) * 2);
                ldsm_x4(t4, ad);
                klf[2 * gg][0] = t4[0]; klf[2 * gg][1] = t4[2];
                klf[2 * gg + 1][0] = t4[1]; klf[2 * gg + 1][1] = t4[3];
            }
#pragma unroll
            for (int j = 0; j < 8; ++j) mma16816(s[j], ah[ks], klf[j]);
        }

        // ---- + mask ----
#pragma unroll
        for (int j = 0; j < 8; ++j) {
            float2 u0 = *(const float2*)(mp0 + j * 8);
            float2 u1 = *(const float2*)(mp1 + j * 8);
            s[j][0] += u0.x; s[j][1] += u0.y;
            s[j][2] += u1.x; s[j][3] += u1.y;
        }

        // ---- online softmax (rows g on FMA poly, rows g+8 on MUFU) ----
        float mx0 = -1e30f, mx1 = -1e30f;
#pragma unroll
        for (int j = 0; j < 8; ++j) {
            mx0 = fmaxf(mx0, fmaxf(s[j][0], s[j][1]));
            mx1 = fmaxf(mx1, fmaxf(s[j][2], s[j][3]));
        }
        mx0 = fmaxf(mx0, __shfl_xor_sync(0xffffffffu, mx0, 1));
        mx0 = fmaxf(mx0, __shfl_xor_sync(0xffffffffu, mx0, 2));
        mx1 = fmaxf(mx1, __shfl_xor_sync(0xffffffffu, mx1, 1));
        mx1 = fmaxf(mx1, __shfl_xor_sync(0xffffffffu, mx1, 2));
        float nm0 = fmaxf(m0, mx0), nm1 = fmaxf(m1, mx1);
        float a0 = exp2p((m0 - nm0) * L2E);
        float a1 = ex2m((m1 - nm1) * L2E);
        m0 = nm0; m1 = nm1;
        float b0 = nm0 * L2E, b1 = nm1 * L2E;
        float nl0 = 0.0f, nl1 = 0.0f;
#pragma unroll
        for (int j = 0; j < 8; ++j) {
            s[j][0] = exp2p(fmaf(s[j][0], L2E, -b0));   // FMA pipe
            s[j][1] = exp2p(fmaf(s[j][1], L2E, -b0));
            s[j][2] = ex2m(fmaf(s[j][2], L2E, -b1));    // MUFU pipe
            s[j][3] = ex2m(fmaf(s[j][3], L2E, -b1));
            nl0 += s[j][0] + s[j][1];
            nl1 += s[j][2] + s[j][3];
        }
        nl0 += __shfl_xor_sync(0xffffffffu, nl0, 1);
        nl0 += __shfl_xor_sync(0xffffffffu, nl0, 2);
        nl1 += __shfl_xor_sync(0xffffffffu, nl1, 1);
        nl1 += __shfl_xor_sync(0xffffffffu, nl1, 2);
        l0 = l0 * a0 + nl0;
        l1 = l1 * a1 + nl1;

        // ---- P -> split A-frags ----
        uint32_t ph[4][4], pl[4][4];
#pragma unroll
        for (int k2 = 0; k2 < 4; ++k2) {
            split2(s[2 * k2][0],     s[2 * k2][1],     ph[k2][0], pl[k2][0]);
            split2(s[2 * k2][2],     s[2 * k2][3],     ph[k2][1], pl[k2][1]);
            split2(s[2 * k2 + 1][0], s[2 * k2 + 1][1], ph[k2][2], pl[k2][2]);
            split2(s[2 * k2 + 1][2], s[2 * k2 + 1][3], ph[k2][3], pl[k2][3]);
        }

        // ---- rescale O ----
#pragma unroll
        for (int nf = 0; nf < 16; ++nf) {
            o[nf][0] *= a0; o[nf][1] *= a0;
            o[nf][2] *= a1; o[nf][3] *= a1;
        }

        // ---- V_ci ready? wait (K_{ci+1} group may remain in flight) ----
        if (ci + 1 < NT) cp_wait<1>(); else cp_wait<0>();
        __syncthreads();

        // ---- O += P @ V (ph*vh + pl*vh + ph*vl) ----
#pragma unroll
        for (int k2 = 0; k2 < 4; ++k2) {
#pragma unroll
            for (int half = 0; half < 2; ++half) {
                uint32_t t4[4], vhf[8][2];
#pragma unroll
                for (int gi = 0; gi < 4; ++gi) {
                    int n0 = (half * 4 + gi) * 16;
                    uint32_t ad = sb + (uint32_t)((VH_E6 + (k2 * 16 + la) * FSe6 + n0 + lb * 8) * 2);
                    ldsm_x4_t(t4, ad);
                    vhf[2 * gi][0] = t4[0]; vhf[2 * gi][1] = t4[1];
                    vhf[2 * gi + 1][0] = t4[2]; vhf[2 * gi + 1][1] = t4[3];
                }
#pragma unroll
                for (int f = 0; f < 8; ++f) mma16816(o[half * 8 + f], ph[k2], vhf[f]);
#pragma unroll
                for (int f = 0; f < 8; ++f) mma16816(o[half * 8 + f], pl[k2], vhf[f]);
                uint32_t vlf[8][2];
#pragma unroll
                for (int gi = 0; gi < 4; ++gi) {
                    int n0 = (half * 4 + gi) * 16;
                    uint32_t ad = sb + (uint32_t)((VL_E6 + (k2 * 16 + la) * FSe6 + n0 + lb * 8) * 2);
                    ldsm_x4_t(t4, ad);
                    vlf[2 * gi][0] = t4[0]; vlf[2 * gi][1] = t4[1];
                    vlf[2 * gi + 1][0] = t4[2]; vlf[2 * gi + 1][1] = t4[3];
                }
#pragma unroll
                for (int f = 0; f < 8; ++f) mma16816(o[half * 8 + f], ph[k2], vlf[f]);
            }
        }
    }

    // ---- finalize: O / l -> split bf16 att ----
    float il0 = 1.0f / l0, il1 = 1.0f / l1;
    size_t base0 = ((size_t)(b * S_ + q0 + qr + g)) * D_ + h * HD_ + 2 * t;
    size_t base1 = base0 + 8 * (size_t)D_;
#pragma unroll
    for (int nf = 0; nf < 16; ++nf) {
        uint32_t hi, lo;
        split2(o[nf][0] * il0, o[nf][1] * il0, hi, lo);
        *(uint32_t*)(g_ath + base0 + nf * 8) = hi;
        *(uint32_t*)(g_atl + base0 + nf * 8) = lo;
        split2(o[nf][2] * il1, o[nf][3] * il1, hi, lo);
        *(uint32_t*)(g_ath + base1 + nf * 8) = hi;
        *(uint32_t*)(g_atl + base1 + nf * 8) = lo;
    }
}

// ---------------------------------------------------------------------------
extern "C" void kernel_launch(void* const* d_in, const int* in_sizes, int n_in,
                              void* d_out, int out_size)
{
    (void)in_sizes; (void)n_in; (void)out_size;
    const float* x    = (const float*)d_in[0];
    const float* mask = (const float*)d_in[1];
    const float* wq_w = (const float*)d_in[2];
    const float* wq_b = (const float*)d_in[3];
    const float* wk_w = (const float*)d_in[4];
    const float* wk_b = (const float*)d_in[5];
    const float* wv_w = (const float*)d_in[6];
    const float* wv_b = (const float*)d_in[7];
    const float* wo_w = (const float*)d_in[8];
    const float* wo_b = (const float*)d_in[9];
    float* out = (float*)d_out;

    cudaFuncSetAttribute(tc_gemm3,    cudaFuncAttributeMaxDynamicSharedMemorySize, SMEM_G2);
    cudaFuncSetAttribute(flash_hmma9, cudaFuncAttributeMaxDynamicSharedMemorySize, SMEM_FL6);

    // prepass: split all fp32 inputs -> bf16 hi/lo (one launch)
    split_all<<<16896, 256>>>(x, wq_w, wk_w, wv_w, wo_w);
    // merged projection: Q (prescaled split), K, V in one launch
    tc_gemm3<<<dim3(18, 32, 1), dim3(256), SMEM_G2>>>(0, wq_b, wk_b, wv_b, nullptr);
    // attention -> split bf16 att (one 256-thread CTA = 8 warps/SM, no reg cap)
    flash_hmma9<<<dim3(S_ / 128, H_, B_), dim3(256), SMEM_FL6>>>(mask);
    // out = att @ wo + bo (fp32)
    tc_gemm3<<<dim3(16, 32, 1), dim3(256), SMEM_G2>>>(1, wo_b, nullptr, nullptr, out);
}

// round 17
// speedup vs baseline: 1.0655x; 1.0655x over previous
#include <cuda_runtime.h>
#include <cuda_bf16.h>
#include <cstdint>
#include <math.h>

// Problem constants
constexpr int B_  = 2;
constexpr int S_  = 2048;
constexpr int D_  = 2048;
constexpr int H_  = 16;
constexpr int HD_ = 128;

// ---- pre-split bf16 scratch (device globals; no allocation allowed) ----
__device__ __nv_bfloat16 g_xh [(size_t)B_ * S_ * D_], g_xl [(size_t)B_ * S_ * D_];
__device__ __nv_bfloat16 g_wqh[(size_t)D_ * D_],      g_wql[(size_t)D_ * D_];
__device__ __nv_bfloat16 g_wkh[(size_t)D_ * HD_],     g_wkl[(size_t)D_ * HD_];
__device__ __nv_bfloat16 g_wvh[(size_t)D_ * HD_],     g_wvl[(size_t)D_ * HD_];
__device__ __nv_bfloat16 g_woh[(size_t)D_ * D_],      g_wol[(size_t)D_ * D_];
__device__ __nv_bfloat16 g_qh [(size_t)B_ * S_ * D_], g_ql [(size_t)B_ * S_ * D_];
__device__ __nv_bfloat16 g_kh [(size_t)B_ * S_ * HD_], g_kl [(size_t)B_ * S_ * HD_];
__device__ __nv_bfloat16 g_vh [(size_t)B_ * S_ * HD_], g_vl [(size_t)B_ * S_ * HD_];
__device__ __nv_bfloat16 g_ath[(size_t)B_ * S_ * D_], g_atl[(size_t)B_ * S_ * D_];

// ===========================================================================
// PTX helpers — baseline ISA only (mma.sync sm_80+, ldmatrix, cp.async).
// ===========================================================================
__device__ __forceinline__ uint32_t smem_u32(const void* p) {
    uint32_t a;
    asm("{ .reg .u64 t; cvta.to.shared.u64 t, %1; cvt.u32.u64 %0, t; }"
        : "=r"(a) : "l"(p));
    return a;
}
__device__ __forceinline__ void ldsm_x4(uint32_t* r, uint32_t addr) {
    asm volatile("ldmatrix.sync.aligned.m8n8.x4.shared.b16 {%0,%1,%2,%3}, [%4];"
                 : "=r"(r[0]), "=r"(r[1]), "=r"(r[2]), "=r"(r[3]) : "r"(addr));
}
__device__ __forceinline__ void ldsm_x4_t(uint32_t* r, uint32_t addr) {
    asm volatile("ldmatrix.sync.aligned.m8n8.x4.trans.shared.b16 {%0,%1,%2,%3}, [%4];"
                 : "=r"(r[0]), "=r"(r[1]), "=r"(r[2]), "=r"(r[3]) : "r"(addr));
}
__device__ __forceinline__ void mma16816(float* c, const uint32_t* a, const uint32_t* b) {
    asm volatile(
        "mma.sync.aligned.m16n8k16.row.col.f32.bf16.bf16.f32 "
        "{%0,%1,%2,%3}, {%4,%5,%6,%7}, {%8,%9}, {%0,%1,%2,%3};"
        : "+f"(c[0]), "+f"(c[1]), "+f"(c[2]), "+f"(c[3])
        : "r"(a[0]), "r"(a[1]), "r"(a[2]), "r"(a[3]), "r"(b[0]), "r"(b[1]));
}
__device__ __forceinline__ void cp16(uint32_t dst, const void* src) {
    asm volatile("cp.async.cg.shared.global [%0], [%1], 16;" :: "r"(dst), "l"(src));
}
#define CP_COMMIT() asm volatile("cp.async.commit_group;" ::: "memory")
template<int N> __device__ __forceinline__ void cp_wait() {
    asm volatile("cp.async.wait_group %0;" :: "n"(N) : "memory");
}

__device__ __forceinline__ void split4(float4 v, uint2& hp, uint2& lp) {
    __nv_bfloat16 hx = __float2bfloat16(v.x), hy = __float2bfloat16(v.y);
    __nv_bfloat16 hz = __float2bfloat16(v.z), hw = __float2bfloat16(v.w);
    __nv_bfloat16 lx = __float2bfloat16(v.x - __bfloat162float(hx));
    __nv_bfloat16 ly = __float2bfloat16(v.y - __bfloat162float(hy));
    __nv_bfloat16 lz = __float2bfloat16(v.z - __bfloat162float(hz));
    __nv_bfloat16 lw = __float2bfloat16(v.w - __bfloat162float(hw));
    hp.x = (uint32_t)__bfloat16_as_ushort(hx) | ((uint32_t)__bfloat16_as_ushort(hy) << 16);
    hp.y = (uint32_t)__bfloat16_as_ushort(hz) | ((uint32_t)__bfloat16_as_ushort(hw) << 16);
    lp.x = (uint32_t)__bfloat16_as_ushort(lx) | ((uint32_t)__bfloat16_as_ushort(ly) << 16);
    lp.y = (uint32_t)__bfloat16_as_ushort(lz) | ((uint32_t)__bfloat16_as_ushort(lw) << 16);
}
// split2 via packed bf16x2 cvt: hi = pack(bf16(y), bf16(x)); residuals from
// bit-level unpack (bf16 f32 bits == bf16 bits << 16). Same RNE rounding as
// __float2bfloat16 -> bit-identical results, ~6 instrs vs ~10.
__device__ __forceinline__ void split2(float x, float y, uint32_t& hi, uint32_t& lo) {
    uint32_t h;
    asm("cvt.rn.bf16x2.f32 %0, %1, %2;" : "=r"(h) : "f"(y), "f"(x));
    float hx_f = __uint_as_float(h << 16);
    float hy_f = __uint_as_float(h & 0xffff0000u);
    float lx = x - hx_f;
    float ly = y - hy_f;
    uint32_t l;
    asm("cvt.rn.bf16x2.f32 %0, %1, %2;" : "=r"(l) : "f"(ly), "f"(lx));
    hi = h; lo = l;
}

// exp2 on the FMA pipe: deg-5 poly, rel err ~2e-6.
__device__ __forceinline__ float exp2p(float y) {
    y = fmaxf(y, -126.0f);
    float k = rintf(y);
    float f = y - k;
    float p = 1.3333558146e-3f;
    p = fmaf(p, f, 9.6181291058e-3f);
    p = fmaf(p, f, 5.5504108664e-2f);
    p = fmaf(p, f, 2.4022650696e-1f);
    p = fmaf(p, f, 6.9314718056e-1f);
    p = fmaf(p, f, 1.0f);
    return p * __int_as_float(((int)k + 127) << 23);
}
// exp2 on the MUFU pipe (pipe-balance with exp2p). Proven accuracy-safe.
__device__ __forceinline__ float ex2m(float y) {
    float r;
    asm("ex2.approx.ftz.f32 %0, %1;" : "=f"(r) : "f"(y));
    return r;
}

// ===========================================================================
// Prepass (single launch): fp32 -> (hi, lo) bf16, all 5 arrays.
// ===========================================================================
__global__ void split_all(const float* __restrict__ x,  const float* __restrict__ wq,
                          const float* __restrict__ wk, const float* __restrict__ wv,
                          const float* __restrict__ wo)
{
    int bx = blockIdx.x;
    const float* src; __nv_bfloat16 *h, *l; int off;
    if (bx < 8192)       { src = x;  h = g_xh;  l = g_xl;  off = bx; }
    else if (bx < 12288) { src = wq; h = g_wqh; l = g_wql; off = bx - 8192; }
    else if (bx < 12544) { src = wk; h = g_wkh; l = g_wkl; off = bx - 12288; }
    else if (bx < 12800) { src = wv; h = g_wvh; l = g_wvl; off = bx - 12544; }
    else                 { src = wo; h = g_woh; l = g_wol; off = bx - 12800; }
    size_t i = ((size_t)off * 256 + threadIdx.x) * 4;
    float4 v = *(const float4*)(src + i);
    uint2 hp, lp;
    split4(v, hp, lp);
    *(uint2*)(h + i) = hp;
    *(uint2*)(l + i) = lp;
}

// ===========================================================================
// tc_gemm3: bf16-split HMMA GEMM, cp.async 3-stage pipe, region-decoded.
// (structure unchanged — tensor 57%; epilogue uses the cheaper split2)
// ===========================================================================
constexpr int KC2  = 32;
constexpr int SAe  = 40;
constexpr int SBe  = 136;
constexpr int AL_E = 128 * SAe;
constexpr int BH_E = 2 * 128 * SAe;
constexpr int BL_E = BH_E + KC2 * SBe;
constexpr int STG_E = BL_E + KC2 * SBe;
constexpr int SMEM_G2 = 3 * STG_E * 2;

__global__ __launch_bounds__(256)
void tc_gemm3(int mode, const float* __restrict__ biasQ, const float* __restrict__ biasK,
              const float* __restrict__ biasV, float* __restrict__ CfOut)
{
    const int bx = blockIdx.x;
    const __nv_bfloat16 *Agh, *Agl, *Bgh, *Bgl;
    const float* bia;
    __nv_bfloat16 *Ch = nullptr, *Cl = nullptr;
    float* Cf = nullptr;
    int NW, colL;
    float osc = 1.0f;
    if (mode == 0) {
        Agh = g_xh; Agl = g_xl;
        if (bx < 16) {
            Bgh = g_wqh; Bgl = g_wql; bia = biasQ; NW = D_;  colL = bx * 128;
            Ch = g_qh; Cl = g_ql; osc = 0.08838834764831845f;
        } else if (bx == 16) {
            Bgh = g_wkh; Bgl = g_wkl; bia = biasK; NW = HD_; colL = 0;
            Ch = g_kh; Cl = g_kl;
        } else {
            Bgh = g_wvh; Bgl = g_wvl; bia = biasV; NW = HD_; colL = 0;
            Ch = g_vh; Cl = g_vl;
        }
    } else {
        Agh = g_ath; Agl = g_atl;
        Bgh = g_woh; Bgl = g_wol; bia = biasQ; NW = D_; colL = bx * 128;
        Cf = CfOut;
    }
    const int K = D_;

    extern __shared__ unsigned short smu[];
    const uint32_t sb = smem_u32(smu);
    const int tid  = threadIdx.x;
    const int wid  = tid >> 5;
    const int lane = tid & 31;
    const int row0 = blockIdx.y * 128;

    const int wm = wid >> 2;
    const int wn = wid & 3;
    const int la = lane & 15;
    const int lb = lane >> 4;

    uint32_t offA[4], offB4[2];
#pragma unroll
    for (int mi = 0; mi < 4; ++mi)
        offA[mi] = (uint32_t)(((wm * 64 + mi * 16 + la) * SAe + lb * 8) * 2);
#pragma unroll
    for (int p = 0; p < 2; ++p)
        offB4[p] = (uint32_t)((la * SBe + wn * 32 + p * 16 + lb * 8) * 2);

    auto issue = [&](int c, int stg) {
        const int kc = c * KC2;
        const uint32_t sbase = sb + (uint32_t)(stg * STG_E) * 2;
#pragma unroll
        for (int u = 0; u < 2; ++u) {
            int ci2 = u * 256 + tid;
            int r = ci2 >> 2, p = ci2 & 3;
            uint32_t doff = (uint32_t)((r * SAe + p * 8) * 2);
            const size_t gsrc = (size_t)(row0 + r) * K + kc + p * 8;
            cp16(sbase + doff, Agh + gsrc);
            cp16(sbase + AL_E * 2 + doff, Agl + gsrc);
        }
#pragma unroll
        for (int u = 0; u < 2; ++u) {
            int ci2 = u * 256 + tid;
            int k = ci2 >> 4, p = ci2 & 15;
            uint32_t doff = (uint32_t)((k * SBe + p * 8) * 2);
            const size_t gsrc = (size_t)(kc + k) * NW + colL + p * 8;
            cp16(sbase + BH_E * 2 + doff, Bgh + gsrc);
            cp16(sbase + BL_E * 2 + doff, Bgl + gsrc);
        }
    };

    float acc[4][4][4];
#pragma unroll
    for (int mi = 0; mi < 4; ++mi)
#pragma unroll
        for (int ni = 0; ni < 4; ++ni)
#pragma unroll
            for (int r = 0; r < 4; ++r) acc[mi][ni][r] = 0.0f;

    issue(0, 0); CP_COMMIT();
    issue(1, 1); CP_COMMIT();

    const int NCH = K / KC2;
    for (int ci = 0; ci < NCH; ++ci) {
        cp_wait<1>();
        __syncthreads();
        if (ci + 2 < NCH) { issue(ci + 2, (ci + 2) % 3); CP_COMMIT(); }

        const uint32_t bAh = sb + (uint32_t)((ci % 3) * STG_E) * 2;
        const uint32_t bAl = bAh + AL_E * 2;
        const uint32_t bBh = sb + (uint32_t)((ci % 3) * STG_E + BH_E) * 2;
        const uint32_t bBl = bBh + (BL_E - BH_E) * 2;

#pragma unroll
        for (int kk = 0; kk < 2; ++kk) {
            const uint32_t dA = (uint32_t)(kk * 16 * 2);
            const uint32_t dB = (uint32_t)(kk * 16 * SBe * 2);
            uint32_t ah[4][4], al[4][4], bh[4][2], bl[4][2], t4[4];
#pragma unroll
            for (int mi = 0; mi < 4; ++mi) {
                ldsm_x4(ah[mi], bAh + offA[mi] + dA);
                ldsm_x4(al[mi], bAl + offA[mi] + dA);
            }
#pragma unroll
            for (int p = 0; p < 2; ++p) {
                ldsm_x4_t(t4, bBh + offB4[p] + dB);
                bh[2 * p][0] = t4[0]; bh[2 * p][1] = t4[1];
                bh[2 * p + 1][0] = t4[2]; bh[2 * p + 1][1] = t4[3];
                ldsm_x4_t(t4, bBl + offB4[p] + dB);
                bl[2 * p][0] = t4[0]; bl[2 * p][1] = t4[1];
                bl[2 * p + 1][0] = t4[2]; bl[2 * p + 1][1] = t4[3];
            }
#pragma unroll
            for (int mi = 0; mi < 4; ++mi)
#pragma unroll
                for (int ni = 0; ni < 4; ++ni)
                    mma16816(acc[mi][ni], ah[mi], bh[ni]);
#pragma unroll
            for (int mi = 0; mi < 4; ++mi)
#pragma unroll
                for (int ni = 0; ni < 4; ++ni)
                    mma16816(acc[mi][ni], ah[mi], bl[ni]);
#pragma unroll
            for (int mi = 0; mi < 4; ++mi)
#pragma unroll
                for (int ni = 0; ni < 4; ++ni)
                    mma16816(acc[mi][ni], al[mi], bh[ni]);
        }
    }

    const int g = lane >> 2, t = lane & 3;
    if (Cf) {
#pragma unroll
        for (int mi = 0; mi < 4; ++mi)
#pragma unroll
            for (int ni = 0; ni < 4; ++ni) {
                int row = row0 + wm * 64 + mi * 16 + g;
                int col = colL + wn * 32 + ni * 8 + 2 * t;
                float b0v = bia[col], b1v = bia[col + 1];
                *(float2*)&Cf[(size_t)row * NW + col] =
                    make_float2(acc[mi][ni][0] + b0v, acc[mi][ni][1] + b1v);
                *(float2*)&Cf[(size_t)(row + 8) * NW + col] =
                    make_float2(acc[mi][ni][2] + b0v, acc[mi][ni][3] + b1v);
            }
    } else {
#pragma unroll
        for (int mi = 0; mi < 4; ++mi)
#pragma unroll
            for (int ni = 0; ni < 4; ++ni) {
                int row = row0 + wm * 64 + mi * 16 + g;
                int col = colL + wn * 32 + ni * 8 + 2 * t;
                float b0v = bia[col], b1v = bia[col + 1];
                uint32_t hi, lo;
                split2((acc[mi][ni][0] + b0v) * osc, (acc[mi][ni][1] + b1v) * osc, hi, lo);
                *(uint32_t*)(Ch + (size_t)row * NW + col) = hi;
                *(uint32_t*)(Cl + (size_t)row * NW + col) = lo;
                split2((acc[mi][ni][2] + b0v) * osc, (acc[mi][ni][3] + b1v) * osc, hi, lo);
                *(uint32_t*)(Ch + (size_t)(row + 8) * NW + col) = hi;
                *(uint32_t*)(Cl + (size_t)(row + 8) * NW + col) = lo;
            }
    }
}

// ===========================================================================
// flash_hmma6 (R13 proven-best shape, byte-for-byte structure): 128 threads,
// 64 q-rows, Bc=64, K double-buffered in the dead Q region, V single-
// buffered, mixed-pipe exp. Mask L2-prefetch dropped (R14 proved mask path
// costs ~0; the prefetches were pure issue overhead).
// ===========================================================================
constexpr int FSe6  = 136;
constexpr int RA_E  = 0;
constexpr int RB_E  = 17408;
constexpr int VH_E6 = 34816;
constexpr int VL_E6 = 43520;
constexpr int HALF_T = 8704;               // one hi (or lo) K/Q tensor: 64*136
constexpr int SMEM_FL6 = 52224 * 2;        // 104448 B

__global__ __launch_bounds__(128)
void flash_hmma6(const float* __restrict__ mask)
{
    extern __shared__ unsigned short smu[];
    const uint32_t sb = smem_u32(smu);
    const int tid  = threadIdx.x;
    const int wid  = tid >> 5;
    const int lane = tid & 31;
    const int q0 = blockIdx.x * 64;
    const int h  = blockIdx.y;
    const int b  = blockIdx.z;
    const int qr = wid * 16;
    const int g  = lane >> 2;
    const int t  = lane & 3;
    const int la = lane & 15;
    const int lb = lane >> 4;
    const float L2E = 1.4426950408889634f;

    auto issueT = [&](const __nv_bfloat16* srcH, const __nv_bfloat16* srcL,
                      uint32_t dstE, int row0g) {
#pragma unroll
        for (int u = 0; u < 8; ++u) {
            int ci2 = u * 128 + tid;
            int r = ci2 >> 4, p = ci2 & 15;
            const size_t gsrc = ((size_t)(b * S_ + row0g + r)) * HD_ + p * 8;
            uint32_t doff = (uint32_t)((r * FSe6 + p * 8) * 2);
            cp16(sb + dstE * 2 + doff, srcH + gsrc);
            cp16(sb + (dstE + HALF_T) * 2 + doff, srcL + gsrc);
        }
    };

    // ---- prologue: Q -> RA, K0 -> RB ----
    {
#pragma unroll
        for (int u = 0; u < 8; ++u) {
            int ci2 = u * 128 + tid;
            int r = ci2 >> 4, p = ci2 & 15;
            const size_t gsrc = ((size_t)(b * S_ + q0 + r)) * D_ + h * HD_ + p * 8;
            uint32_t doff = (uint32_t)((r * FSe6 + p * 8) * 2);
            cp16(sb + doff, g_qh + gsrc);
            cp16(sb + HALF_T * 2 + doff, g_ql + gsrc);
        }
        CP_COMMIT();
        issueT(g_kh, g_kl, RB_E, 0);
        CP_COMMIT();
    }
    cp_wait<0>();
    __syncthreads();

    // ---- Q A-frags to registers (persist); RA free after tile-0 sync ----
    uint32_t ah[8][4], al[8][4];
#pragma unroll
    for (int ks = 0; ks < 8; ++ks) {
        uint32_t ad = sb + (uint32_t)(((qr + la) * FSe6 + ks * 16 + lb * 8) * 2);
        ldsm_x4(ah[ks], ad);
        ldsm_x4(al[ks], ad + HALF_T * 2);
    }

    float m0 = -1e30f, m1 = -1e30f, l0 = 0.0f, l1 = 0.0f;
    float o[16][4];
#pragma unroll
    for (int nf = 0; nf < 16; ++nf)
#pragma unroll
        for (int r = 0; r < 4; ++r) o[nf][r] = 0.0f;

    constexpr int NT = S_ / 64;
    for (int ci = 0; ci < NT; ++ci) {
        cp_wait<0>();
        __syncthreads();

        const uint32_t kBase = (ci & 1) ? (uint32_t)RA_E : (uint32_t)RB_E;

        issueT(g_vh, g_vl, VH_E6, ci * 64);
        CP_COMMIT();
        if (ci + 1 < NT) {
            issueT(g_kh, g_kl, (ci & 1) ? RB_E : RA_E, (ci + 1) * 64);
            CP_COMMIT();
        }

        const int kv0 = ci * 64;
        const float* mp0 = mask + ((size_t)b * S_ + (q0 + qr + g)) * S_ + kv0 + 2 * t;
        const float* mp1 = mp0 + 8 * (size_t)S_;

        // ---- S = Q @ K^T (hh + lh + hl) ----
        float s[8][4];
#pragma unroll
        for (int j = 0; j < 8; ++j)
#pragma unroll
            for (int r = 0; r < 4; ++r) s[j][r] = 0.0f;

#pragma unroll
        for (int ks = 0; ks < 8; ++ks) {
            uint32_t t4[4], khf[8][2];
#pragma unroll
            for (int gg = 0; gg < 4; ++gg) {
                uint32_t ad = sb + (uint32_t)((kBase + (gg * 16 + la) * FSe6 + ks * 16 + lb * 8) * 2);
                ldsm_x4(t4, ad);
                khf[2 * gg][0] = t4[0]; khf[2 * gg][1] = t4[2];
                khf[2 * gg + 1][0] = t4[1]; khf[2 * gg + 1][1] = t4[3];
            }
#pragma unroll
            for (int j = 0; j < 8; ++j) mma16816(s[j], ah[ks], khf[j]);
#pragma unroll
            for (int j = 0; j < 8; ++j) mma16816(s[j], al[ks], khf[j]);
            uint32_t klf[8][2];
#pragma unroll
            for (int gg = 0; gg < 4; ++gg) {
                uint32_t ad = sb + (uint32_t)((kBase + HALF_T + (gg * 16 + la) * FSe6 + ks * 16 + lb * 8) * 2);
                ldsm_x4(t4, ad);
                klf[2 * gg][0] = t4[0]; klf[2 * gg][1] = t4[2];
                klf[2 * gg + 1][0] = t4[1]; klf[2 * gg + 1][1] = t4[3];
            }
#pragma unroll
            for (int j = 0; j < 8; ++j) mma16816(s[j], ah[ks], klf[j]);
        }

        // ---- + mask ----
#pragma unroll
        for (int j = 0; j < 8; ++j) {
            float2 u0 = *(const float2*)(mp0 + j * 8);
            float2 u1 = *(const float2*)(mp1 + j * 8);
            s[j][0] += u0.x; s[j][1] += u0.y;
            s[j][2] += u1.x; s[j][3] += u1.y;
        }

        // ---- online softmax (rows g on FMA poly, rows g+8 on MUFU) ----
        float mx0 = -1e30f, mx1 = -1e30f;
#pragma unroll
        for (int j = 0; j < 8; ++j) {
            mx0 = fmaxf(mx0, fmaxf(s[j][0], s[j][1]));
            mx1 = fmaxf(mx1, fmaxf(s[j][2], s[j][3]));
        }
        mx0 = fmaxf(mx0, __shfl_xor_sync(0xffffffffu, mx0, 1));
        mx0 = fmaxf(mx0, __shfl_xor_sync(0xffffffffu, mx0, 2));
        mx1 = fmaxf(mx1, __shfl_xor_sync(0xffffffffu, mx1, 1));
        mx1 = fmaxf(mx1, __shfl_xor_sync(0xffffffffu, mx1, 2));
        float nm0 = fmaxf(m0, mx0), nm1 = fmaxf(m1, mx1);
        float a0 = exp2p((m0 - nm0) * L2E);
        float a1 = ex2m((m1 - nm1) * L2E);
        m0 = nm0; m1 = nm1;
        float b0 = nm0 * L2E, b1 = nm1 * L2E;
        float nl0 = 0.0f, nl1 = 0.0f;
#pragma unroll
        for (int j = 0; j < 8; ++j) {
            s[j][0] = exp2p(fmaf(s[j][0], L2E, -b0));   // FMA pipe
            s[j][1] = exp2p(fmaf(s[j][1], L2E, -b0));
            s[j][2] = ex2m(fmaf(s[j][2], L2E, -b1));    // MUFU pipe
            s[j][3] = ex2m(fmaf(s[j][3], L2E, -b1));
            nl0 += s[j][0] + s[j][1];
            nl1 += s[j][2] + s[j][3];
        }
        nl0 += __shfl_xor_sync(0xffffffffu, nl0, 1);
        nl0 += __shfl_xor_sync(0xffffffffu, nl0, 2);
        nl1 += __shfl_xor_sync(0xffffffffu, nl1, 1);
        nl1 += __shfl_xor_sync(0xffffffffu, nl1, 2);
        l0 = l0 * a0 + nl0;
        l1 = l1 * a1 + nl1;

        // ---- P -> split A-frags ----
        uint32_t ph[4][4], pl[4][4];
#pragma unroll
        for (int k2 = 0; k2 < 4; ++k2) {
            split2(s[2 * k2][0],     s[2 * k2][1],     ph[k2][0], pl[k2][0]);
            split2(s[2 * k2][2],     s[2 * k2][3],     ph[k2][1], pl[k2][1]);
            split2(s[2 * k2 + 1][0], s[2 * k2 + 1][1], ph[k2][2], pl[k2][2]);
            split2(s[2 * k2 + 1][2], s[2 * k2 + 1][3], ph[k2][3], pl[k2][3]);
        }

        // ---- rescale O ----
#pragma unroll
        for (int nf = 0; nf < 16; ++nf) {
            o[nf][0] *= a0; o[nf][1] *= a0;
            o[nf][2] *= a1; o[nf][3] *= a1;
        }

        // ---- V_ci ready? wait (K_{ci+1} group may remain in flight) ----
        if (ci + 1 < NT) cp_wait<1>(); else cp_wait<0>();
        __syncthreads();

        // ---- O += P @ V (ph*vh + pl*vh + ph*vl) ----
#pragma unroll
        for (int k2 = 0; k2 < 4; ++k2) {
#pragma unroll
            for (int half = 0; half < 2; ++half) {
                uint32_t t4[4], vhf[8][2];
#pragma unroll
                for (int gi = 0; gi < 4; ++gi) {
                    int n0 = (half * 4 + gi) * 16;
                    uint32_t ad = sb + (uint32_t)((VH_E6 + (k2 * 16 + la) * FSe6 + n0 + lb * 8) * 2);
                    ldsm_x4_t(t4, ad);
                    vhf[2 * gi][0] = t4[0]; vhf[2 * gi][1] = t4[1];
                    vhf[2 * gi + 1][0] = t4[2]; vhf[2 * gi + 1][1] = t4[3];
                }
#pragma unroll
                for (int f = 0; f < 8; ++f) mma16816(o[half * 8 + f], ph[k2], vhf[f]);
#pragma unroll
                for (int f = 0; f < 8; ++f) mma16816(o[half * 8 + f], pl[k2], vhf[f]);
                uint32_t vlf[8][2];
#pragma unroll
                for (int gi = 0; gi < 4; ++gi) {
                    int n0 = (half * 4 + gi) * 16;
                    uint32_t ad = sb + (uint32_t)((VL_E6 + (k2 * 16 + la) * FSe6 + n0 + lb * 8) * 2);
                    ldsm_x4_t(t4, ad);
                    vlf[2 * gi][0] = t4[0]; vlf[2 * gi][1] = t4[1];
                    vlf[2 * gi + 1][0] = t4[2]; vlf[2 * gi + 1][1] = t4[3];
                }
#pragma unroll
                for (int f = 0; f < 8; ++f) mma16816(o[half * 8 + f], ph[k2], vlf[f]);
            }
        }
    }

    // ---- finalize: O / l -> split bf16 att ----
    float il0 = 1.0f / l0, il1 = 1.0f / l1;
    size_t base0 = ((size_t)(b * S_ + q0 + qr + g)) * D_ + h * HD_ + 2 * t;
    size_t base1 = base0 + 8 * (size_t)D_;
#pragma unroll
    for (int nf = 0; nf < 16; ++nf) {
        uint32_t hi, lo;
        split2(o[nf][0] * il0, o[nf][1] * il0, hi, lo);
        *(uint32_t*)(g_ath + base0 + nf * 8) = hi;
        *(uint32_t*)(g_atl + base0 + nf * 8) = lo;
        split2(o[nf][2] * il1, o[nf][3] * il1, hi, lo);
        *(uint32_t*)(g_ath + base1 + nf * 8) = hi;
        *(uint32_t*)(g_atl + base1 + nf * 8) = lo;
    }
}

// ---------------------------------------------------------------------------
extern "C" void kernel_launch(void* const* d_in, const int* in_sizes, int n_in,
                              void* d_out, int out_size)
{
    (void)in_sizes; (void)n_in; (void)out_size;
    const float* x    = (const float*)d_in[0];
    const float* mask = (const float*)d_in[1];
    const float* wq_w = (const float*)d_in[2];
    const float* wq_b = (const float*)d_in[3];
    const float* wk_w = (const float*)d_in[4];
    const float* wk_b = (const float*)d_in[5];
    const float* wv_w = (const float*)d_in[6];
    const float* wv_b = (const float*)d_in[7];
    const float* wo_w = (const float*)d_in[8];
    const float* wo_b = (const float*)d_in[9];
    float* out = (float*)d_out;

    cudaFuncSetAttribute(tc_gemm3,    cudaFuncAttributeMaxDynamicSharedMemorySize, SMEM_G2);
    cudaFuncSetAttribute(flash_hmma6, cudaFuncAttributeMaxDynamicSharedMemorySize, SMEM_FL6);

    // prepass: split all fp32 inputs -> bf16 hi/lo (one launch)
    split_all<<<16896, 256>>>(x, wq_w, wk_w, wv_w, wo_w);
    // merged projection: Q (prescaled split), K, V in one launch
    tc_gemm3<<<dim3(18, 32, 1), dim3(256), SMEM_G2>>>(0, wq_b, wk_b, wv_b, nullptr);
    // attention -> split bf16 att (R13 proven-best shape)
    flash_hmma6<<<dim3(S_ / 64, H_, B_), dim3(128), SMEM_FL6>>>(mask);
    // out = att @ wo + bo (fp32)
    tc_gemm3<<<dim3(16, 32, 1), dim3(256), SMEM_G2>>>(1, wo_b, nullptr, nullptr, out);
}